// round 8
// baseline (speedup 1.0000x reference)
#include <cuda_runtime.h>
#include <math.h>

#define MAXN 8192
#define THREADS 256
#define QPT 4
#define QBLK (THREADS * QPT)   // 1024 queries per block
#define SLAB 256               // DB points per slab
#define GRP 16                 // argmin recovery group size
#define MAXJB 32               // max DB slabs (8192/256)
#define BIAS 1024.0f           // keeps biased metric strictly positive

// Scratch (allocation-free rule): per-(dir, jblock) partial min keys.
// key = (dist2_bits << 32) | sigma_bits   (both non-negative floats).
__device__ unsigned long long g_pkey[2][MAXJB][MAXN];
__device__ float g_part[64];

static __device__ __forceinline__ float3 load_pt(const float* __restrict__ P,
                                                 int i, bool xform,
                                                 const float* __restrict__ T) {
    float x = __ldg(&P[3*i]), y = __ldg(&P[3*i+1]), z = __ldg(&P[3*i+2]);
    if (xform) {
        float X = fmaf(T[0], x, fmaf(T[1], y, fmaf(T[2],  z, T[3])));
        float Y = fmaf(T[4], x, fmaf(T[5], y, fmaf(T[6],  z, T[7])));
        float Z = fmaf(T[8], x, fmaf(T[9], y, fmaf(T[10], z, T[11])));
        return make_float3(X, Y, Z);
    }
    return make_float3(x, y, z);
}

// blockIdx.z: 0 => queries=ref, DB=transformed src. 1 => swapped.
// Metric: d' = BIAS + |b|^2 - 2 a.b  (positive => float bits order as u32).
// Hot loop: 3 FFMA + 1 IMNMX per pair. Argmin recovered per 16-j group.
__global__ void __launch_bounds__(THREADS) nn_kernel(
        const float* __restrict__ ref, const float* __restrict__ src,
        const float* __restrict__ T,
        const float* __restrict__ rsig, const float* __restrict__ ssig,
        int n, int m) {
    const int dir = blockIdx.z;
    const float* Apts = dir ? src : ref;
    const float* Bpts = dir ? ref : src;
    const float* Bsig = dir ? rsig : ssig;
    const int nA = dir ? m : n;
    const int nB = dir ? n : m;
    const bool xformA = (dir == 1), xformB = (dir == 0);

    __shared__ float4 sBt[SLAB];   // (-2x, -2y, -2z, |b|^2 + BIAS)
    __shared__ float4 sBo[SLAB];   // (x, y, z, sigma) for exact epilogue
    const int tid = threadIdx.x;
    const int jbase = blockIdx.y * SLAB;

    for (int j = tid; j < SLAB; j += THREADS) {
        int gj = jbase + j;
        float3 p = (gj < nB) ? load_pt(Bpts, gj, xformB, T)
                             : make_float3(1e15f, 1e15f, 1e15f);
        float s = (gj < nB) ? __ldg(&Bsig[gj]) : 1.0f;
        sBo[j] = make_float4(p.x, p.y, p.z, s);
        float b2 = fmaf(p.x, p.x, fmaf(p.y, p.y, p.z * p.z));
        sBt[j] = make_float4(-2.0f * p.x, -2.0f * p.y, -2.0f * p.z, b2 + BIAS);
    }

    float ax[QPT], ay[QPT], az[QPT];
    unsigned bestv[QPT];
    int bestg[QPT];
    const int q0 = blockIdx.x * QBLK + tid;
#pragma unroll
    for (int q = 0; q < QPT; q++) {
        int qi = q0 + q * THREADS;
        float3 a = (qi < nA) ? load_pt(Apts, qi, xformA, T)
                             : make_float3(0.f, 0.f, 0.f);
        ax[q] = a.x; ay[q] = a.y; az[q] = a.z;
        bestv[q] = 0xFFFFFFFFu; bestg[q] = 0;
    }
    __syncthreads();

#pragma unroll 1
    for (int g = 0; g < SLAB / GRP; g++) {
        unsigned m0[QPT], m1[QPT];   // alternating accumulators (shorter dep chain)
#pragma unroll
        for (int q = 0; q < QPT; q++) { m0[q] = 0xFFFFFFFFu; m1[q] = 0xFFFFFFFFu; }
#pragma unroll
        for (int u = 0; u < GRP; u++) {
            float4 b = sBt[g * GRP + u];   // broadcast LDS.128
#pragma unroll
            for (int q = 0; q < QPT; q++) {
                float d = fmaf(ax[q], b.x, fmaf(ay[q], b.y, fmaf(az[q], b.z, b.w)));
                unsigned di = __float_as_uint(d);
                if (u & 1) m1[q] = umin(m1[q], di);   // IMNMX.U32 (alu)
                else       m0[q] = umin(m0[q], di);
            }
        }
#pragma unroll
        for (int q = 0; q < QPT; q++) {
            unsigned gm = umin(m0[q], m1[q]);
            if (gm < bestv[q]) { bestv[q] = gm; bestg[q] = g; }
        }
    }

    // Recovery: re-scan winning 16-j group for the bit-exact match, then exact d^2.
#pragma unroll 1
    for (int q = 0; q < QPT; q++) {
        int qi = q0 + q * THREADS;
        if (qi < nA) {
            int jg = bestg[q] * GRP;
            int bj = jg;
#pragma unroll 1
            for (int u = 0; u < GRP; u++) {
                float4 b = sBt[jg + u];
                float d = fmaf(ax[q], b.x, fmaf(ay[q], b.y, fmaf(az[q], b.z, b.w)));
                if (__float_as_uint(d) == bestv[q]) bj = jg + u;
            }
            float4 b = sBo[bj];
            float dx = ax[q] - b.x, dy = ay[q] - b.y, dz = az[q] - b.z;
            float d2 = fmaf(dx, dx, fmaf(dy, dy, dz * dz));
            unsigned long long key =
                (((unsigned long long)__float_as_uint(d2)) << 32) |
                (unsigned long long)__float_as_uint(b.w);
            g_pkey[dir][blockIdx.y][qi] = key;   // no atomics
        }
    }
}

// Stage 1: one thread per query (fwd then bwd concatenated); scan slab partials.
__global__ void __launch_bounds__(256) reduce1_kernel(
        const float* __restrict__ rsig, const float* __restrict__ ssig,
        int n, int m) {
    __shared__ float wsum[8];
    int idx = blockIdx.x * 256 + threadIdx.x;
    float acc = 0.0f;
    if (idx < n + m) {
        int dir = (idx < n) ? 0 : 1;
        int i = (idx < n) ? idx : idx - n;
        int nB = dir ? n : m;
        int njb = (nB + SLAB - 1) / SLAB;
        unsigned long long k = ~0ULL;
        for (int jb = 0; jb < njb; jb++) {
            unsigned long long v = g_pkey[dir][jb][i];
            k = (v < k) ? v : k;
        }
        float self = dir ? __ldg(&ssig[i]) : __ldg(&rsig[i]);
        float d   = sqrtf(__uint_as_float((unsigned)(k >> 32)));
        float sig = 0.5f * (self + __uint_as_float((unsigned)k));
        float inv = dir ? (1.0f / (float)m) : (1.0f / (float)n);
        acc = (__logf(sig) + __fdividef(d, sig)) * inv;
    }
#pragma unroll
    for (int o = 16; o > 0; o >>= 1)
        acc += __shfl_xor_sync(0xFFFFFFFF, acc, o);
    if ((threadIdx.x & 31) == 0) wsum[threadIdx.x >> 5] = acc;
    __syncthreads();
    if (threadIdx.x < 8) {
        float v = wsum[threadIdx.x];
#pragma unroll
        for (int o = 4; o > 0; o >>= 1)
            v += __shfl_xor_sync(0xFF, v, o);
        if (threadIdx.x == 0) g_part[blockIdx.x] = v;
    }
}

__global__ void reduce2_kernel(float* __restrict__ out, int nblocks) {
    int tid = threadIdx.x;   // 64 threads
    __shared__ float s2[2];
    float v = (tid < nblocks) ? g_part[tid] : 0.0f;
#pragma unroll
    for (int o = 16; o > 0; o >>= 1)
        v += __shfl_xor_sync(0xFFFFFFFF, v, o);
    if ((tid & 31) == 0) s2[tid >> 5] = v;
    __syncthreads();
    if (tid == 0) out[0] = s2[0] + s2[1];
}

extern "C" void kernel_launch(void* const* d_in, const int* in_sizes, int n_in,
                              void* d_out, int out_size) {
    const float* ref  = (const float*)d_in[0];
    const float* src  = (const float*)d_in[1];
    const float* T    = (const float*)d_in[2];
    const float* rsig = (const float*)d_in[3];
    const float* ssig = (const float*)d_in[4];
    int n = in_sizes[3];
    int m = in_sizes[4];

    int nm = n > m ? n : m;
    dim3 g((nm + QBLK - 1) / QBLK, (nm + SLAB - 1) / SLAB, 2);
    nn_kernel<<<g, THREADS>>>(ref, src, T, rsig, ssig, n, m);

    int rblocks = (n + m + 255) / 256;
    reduce1_kernel<<<rblocks, 256>>>(rsig, ssig, n, m);
    reduce2_kernel<<<1, 64>>>((float*)d_out, rblocks);
}

// round 10
// speedup vs baseline: 1.0390x; 1.0390x over previous
#include <cuda_runtime.h>
#include <math.h>

#define MAXN 8192
#define THREADS 256
#define QPT 4
#define QBLK (THREADS * QPT)   // 1024 queries per block
#define SLAB 256               // DB points per slab
#define GRP 16                 // group size; 4-bit local index embedded in mantissa
#define MAXJB 32               // max DB slabs (8192/256)

// Scratch (allocation-free rule): per-(dir, jblock) partial min keys.
// key = (dist2_bits << 32) | sigma_bits   (both non-negative floats).
__device__ unsigned long long g_pkey[2][MAXJB][MAXN];
__device__ float g_part[64];

static __device__ __forceinline__ float3 load_pt(const float* __restrict__ P,
                                                 int i, bool xform,
                                                 const float* __restrict__ T) {
    float x = __ldg(&P[3*i]), y = __ldg(&P[3*i+1]), z = __ldg(&P[3*i+2]);
    if (xform) {
        float X = fmaf(T[0], x, fmaf(T[1], y, fmaf(T[2],  z, T[3])));
        float Y = fmaf(T[4], x, fmaf(T[5], y, fmaf(T[6],  z, T[7])));
        float Z = fmaf(T[8], x, fmaf(T[9], y, fmaf(T[10], z, T[11])));
        return make_float3(X, Y, Z);
    }
    return make_float3(x, y, z);
}

// blockIdx.z: 0 => queries=ref, DB=transformed src. 1 => swapped.
// Metric: d' = |b|^2 - 2 a.b (query-constant |a|^2 dropped: argmin-safe).
// Hot loop per pair: 3 FFMA (fma) + 1 LOP3 + 1 FMNMX (alu).
// 4-bit group-local index lives in the low mantissa bits of the tracked min;
// perturbation <= 15 ulp of d' (~6e-5) and the epilogue recomputes exact d^2.
__global__ void __launch_bounds__(THREADS) nn_kernel(
        const float* __restrict__ ref, const float* __restrict__ src,
        const float* __restrict__ T,
        const float* __restrict__ rsig, const float* __restrict__ ssig,
        int n, int m) {
    const int dir = blockIdx.z;
    const float* Apts = dir ? src : ref;
    const float* Bpts = dir ? ref : src;
    const float* Bsig = dir ? rsig : ssig;
    const int nA = dir ? m : n;
    const int nB = dir ? n : m;
    const bool xformA = (dir == 1), xformB = (dir == 0);

    __shared__ float4 sBt[SLAB];   // (-2x, -2y, -2z, |b|^2)
    __shared__ float4 sBo[SLAB];   // (x, y, z, sigma) for exact epilogue
    const int tid = threadIdx.x;
    const int jbase = blockIdx.y * SLAB;

    for (int j = tid; j < SLAB; j += THREADS) {
        int gj = jbase + j;
        float3 p = (gj < nB) ? load_pt(Bpts, gj, xformB, T)
                             : make_float3(1e15f, 1e15f, 1e15f);
        float s = (gj < nB) ? __ldg(&Bsig[gj]) : 1.0f;
        sBo[j] = make_float4(p.x, p.y, p.z, s);
        float b2 = fmaf(p.x, p.x, fmaf(p.y, p.y, p.z * p.z));
        sBt[j] = make_float4(-2.0f * p.x, -2.0f * p.y, -2.0f * p.z, b2);
    }

    float ax[QPT], ay[QPT], az[QPT], bestv[QPT];
    int bestg[QPT];
    const int q0 = blockIdx.x * QBLK + tid;
#pragma unroll
    for (int q = 0; q < QPT; q++) {
        int qi = q0 + q * THREADS;
        float3 a = (qi < nA) ? load_pt(Apts, qi, xformA, T)
                             : make_float3(0.f, 0.f, 0.f);
        ax[q] = a.x; ay[q] = a.y; az[q] = a.z;
        bestv[q] = 3.4e38f; bestg[q] = 0;
    }
    __syncthreads();

#pragma unroll 1
    for (int g = 0; g < SLAB / GRP; g++) {
        float m0[QPT], m1[QPT];   // alternating accumulators (short dep chains)
#pragma unroll
        for (int q = 0; q < QPT; q++) { m0[q] = 3.4e38f; m1[q] = 3.4e38f; }
#pragma unroll
        for (int u = 0; u < GRP; u++) {
            float4 b = sBt[g * GRP + u];   // uniform broadcast LDS.128
#pragma unroll
            for (int q = 0; q < QPT; q++) {
                float d = fmaf(ax[q], b.x, fmaf(ay[q], b.y, fmaf(az[q], b.z, b.w)));
                // one LOP3: clear low 4 mantissa bits, OR in constant u
                float dk = __uint_as_float((__float_as_uint(d) & ~15u) | (unsigned)u);
                if (u & 1) m1[q] = fminf(m1[q], dk);   // FMNMX (alu)
                else       m0[q] = fminf(m0[q], dk);
            }
        }
#pragma unroll
        for (int q = 0; q < QPT; q++) {
            float gm = fminf(m0[q], m1[q]);
            if (gm < bestv[q]) { bestv[q] = gm; bestg[q] = g; }
        }
    }

    // Recovery is arithmetic only: j = 16*bestg + low-4-bits(bestv). Exact d^2 after.
#pragma unroll
    for (int q = 0; q < QPT; q++) {
        int qi = q0 + q * THREADS;
        if (qi < nA) {
            int bj = bestg[q] * GRP + (int)(__float_as_uint(bestv[q]) & 15u);
            float4 b = sBo[bj];
            float dx = ax[q] - b.x, dy = ay[q] - b.y, dz = az[q] - b.z;
            float d2 = fmaf(dx, dx, fmaf(dy, dy, dz * dz));
            unsigned long long key =
                (((unsigned long long)__float_as_uint(d2)) << 32) |
                (unsigned long long)__float_as_uint(b.w);
            g_pkey[dir][blockIdx.y][qi] = key;   // no atomics
        }
    }
}

// Stage 1: one thread per query (fwd then bwd concatenated); scan slab partials.
__global__ void __launch_bounds__(256) reduce1_kernel(
        const float* __restrict__ rsig, const float* __restrict__ ssig,
        int n, int m) {
    __shared__ float wsum[8];
    int idx = blockIdx.x * 256 + threadIdx.x;
    float acc = 0.0f;
    if (idx < n + m) {
        int dir = (idx < n) ? 0 : 1;
        int i = (idx < n) ? idx : idx - n;
        int nB = dir ? n : m;
        int njb = (nB + SLAB - 1) / SLAB;
        unsigned long long k = ~0ULL;
        for (int jb = 0; jb < njb; jb++) {
            unsigned long long v = g_pkey[dir][jb][i];
            k = (v < k) ? v : k;
        }
        float self = dir ? __ldg(&ssig[i]) : __ldg(&rsig[i]);
        float d   = sqrtf(__uint_as_float((unsigned)(k >> 32)));
        float sig = 0.5f * (self + __uint_as_float((unsigned)k));
        float inv = dir ? (1.0f / (float)m) : (1.0f / (float)n);
        acc = (__logf(sig) + __fdividef(d, sig)) * inv;
    }
#pragma unroll
    for (int o = 16; o > 0; o >>= 1)
        acc += __shfl_xor_sync(0xFFFFFFFF, acc, o);
    if ((threadIdx.x & 31) == 0) wsum[threadIdx.x >> 5] = acc;
    __syncthreads();
    if (threadIdx.x < 8) {
        float v = wsum[threadIdx.x];
#pragma unroll
        for (int o = 4; o > 0; o >>= 1)
            v += __shfl_xor_sync(0xFF, v, o);
        if (threadIdx.x == 0) g_part[blockIdx.x] = v;
    }
}

__global__ void reduce2_kernel(float* __restrict__ out, int nblocks) {
    int tid = threadIdx.x;   // 64 threads
    __shared__ float s2[2];
    float v = (tid < nblocks) ? g_part[tid] : 0.0f;
#pragma unroll
    for (int o = 16; o > 0; o >>= 1)
        v += __shfl_xor_sync(0xFFFFFFFF, v, o);
    if ((tid & 31) == 0) s2[tid >> 5] = v;
    __syncthreads();
    if (tid == 0) out[0] = s2[0] + s2[1];
}

extern "C" void kernel_launch(void* const* d_in, const int* in_sizes, int n_in,
                              void* d_out, int out_size) {
    const float* ref  = (const float*)d_in[0];
    const float* src  = (const float*)d_in[1];
    const float* T    = (const float*)d_in[2];
    const float* rsig = (const float*)d_in[3];
    const float* ssig = (const float*)d_in[4];
    int n = in_sizes[3];
    int m = in_sizes[4];

    int nm = n > m ? n : m;
    dim3 g((nm + QBLK - 1) / QBLK, (nm + SLAB - 1) / SLAB, 2);
    nn_kernel<<<g, THREADS>>>(ref, src, T, rsig, ssig, n, m);

    int rblocks = (n + m + 255) / 256;
    reduce1_kernel<<<rblocks, 256>>>(rsig, ssig, n, m);
    reduce2_kernel<<<1, 64>>>((float*)d_out, rblocks);
}

// round 13
// speedup vs baseline: 1.2337x; 1.1874x over previous
#include <cuda_runtime.h>
#include <math.h>

#define NMAX 8192
#define NTHR 128
#define QPER 4
#define QTILE (NTHR * QPER)    // 512 queries per block
#define JTILE 256              // DB points per slab
#define JGRP 16                // group size; 4-bit local index in mantissa
#define JBMAX 32               // max DB slabs (8192/256)

// Scratch (allocation-free rule): per-(dir, jblock) partial min keys.
// key = (dist2_bits << 32) | sigma_bits   (both non-negative floats).
__device__ unsigned long long g_partial_keys[2][JBMAX][NMAX];
__device__ float g_partial_sums[64];

static __device__ __forceinline__ float3 fetch_point(
        const float* __restrict__ P, int i, bool apply_T,
        const float* __restrict__ T) {
    float x = __ldg(&P[3*i]), y = __ldg(&P[3*i+1]), z = __ldg(&P[3*i+2]);
    if (apply_T) {
        float X = fmaf(T[0], x, fmaf(T[1], y, fmaf(T[2],  z, T[3])));
        float Y = fmaf(T[4], x, fmaf(T[5], y, fmaf(T[6],  z, T[7])));
        float Z = fmaf(T[8], x, fmaf(T[9], y, fmaf(T[10], z, T[11])));
        return make_float3(X, Y, Z);
    }
    return make_float3(x, y, z);
}

// One 16-j group: 3 FFMA + LOP3 + FMNMX per pair; index in low 4 mantissa bits.
static __device__ __forceinline__ void scan_group(
        const float4* __restrict__ sBt, int g,
        const float* ax, const float* ay, const float* az,
        float* bestv, int* bestg) {
    float m0[QPER], m1[QPER];
#pragma unroll
    for (int q = 0; q < QPER; q++) { m0[q] = 3.4e38f; m1[q] = 3.4e38f; }
#pragma unroll
    for (int u = 0; u < JGRP; u++) {
        float4 b = sBt[g * JGRP + u];   // uniform broadcast LDS.128
#pragma unroll
        for (int q = 0; q < QPER; q++) {
            float d = fmaf(ax[q], b.x, fmaf(ay[q], b.y, fmaf(az[q], b.z, b.w)));
            float dk = __uint_as_float((__float_as_uint(d) & ~15u) | (unsigned)u);
            if (u & 1) m1[q] = fminf(m1[q], dk);
            else       m0[q] = fminf(m0[q], dk);
        }
    }
#pragma unroll
    for (int q = 0; q < QPER; q++) {
        float gm = fminf(m0[q], m1[q]);
        if (gm < bestv[q]) { bestv[q] = gm; bestg[q] = g; }
    }
}

// blockIdx.z: 0 => queries=ref, DB=transformed src. 1 => swapped.
// Metric: d' = |b|^2 - 2 a.b (query-constant |a|^2 dropped: argmin-safe).
__global__ void __launch_bounds__(NTHR) nn_pass(
        const float* __restrict__ ref, const float* __restrict__ src,
        const float* __restrict__ T,
        const float* __restrict__ rsig, const float* __restrict__ ssig,
        int n, int m) {
    const int dir = blockIdx.z;
    const float* Apts = dir ? src : ref;
    const float* Bpts = dir ? ref : src;
    const float* Bsig = dir ? rsig : ssig;
    const int nA = dir ? m : n;
    const int nB = dir ? n : m;
    const bool xfA = (dir == 1), xfB = (dir == 0);

    __shared__ float4 sBt[JTILE];   // (-2x, -2y, -2z, |b|^2)
    __shared__ float4 sBo[JTILE];   // (x, y, z, sigma) for exact epilogue
    const int tid = threadIdx.x;
    const int jbase = blockIdx.y * JTILE;

    for (int j = tid; j < JTILE; j += NTHR) {
        int gj = jbase + j;
        float3 p = (gj < nB) ? fetch_point(Bpts, gj, xfB, T)
                             : make_float3(1e15f, 1e15f, 1e15f);
        float s = (gj < nB) ? __ldg(&Bsig[gj]) : 1.0f;
        sBo[j] = make_float4(p.x, p.y, p.z, s);
        float b2 = fmaf(p.x, p.x, fmaf(p.y, p.y, p.z * p.z));
        sBt[j] = make_float4(-2.0f * p.x, -2.0f * p.y, -2.0f * p.z, b2);
    }

    float ax[QPER], ay[QPER], az[QPER], bestv[QPER];
    int bestg[QPER];
    const int q0 = blockIdx.x * QTILE + tid;
#pragma unroll
    for (int q = 0; q < QPER; q++) {
        int qi = q0 + q * NTHR;
        float3 a = (qi < nA) ? fetch_point(Apts, qi, xfA, T)
                             : make_float3(0.f, 0.f, 0.f);
        ax[q] = a.x; ay[q] = a.y; az[q] = a.z;
        bestv[q] = 3.4e38f; bestg[q] = 0;
    }
    __syncthreads();

    // group loop, manually paired (x2) to overlap merge chains across groups
#pragma unroll 1
    for (int g = 0; g < JTILE / JGRP; g += 2) {
        scan_group(sBt, g,     ax, ay, az, bestv, bestg);
        scan_group(sBt, g + 1, ax, ay, az, bestv, bestg);
    }

    // Recovery is arithmetic only: j = 16*bestg + low-4-bits(bestv). Exact d^2.
#pragma unroll
    for (int q = 0; q < QPER; q++) {
        int qi = q0 + q * NTHR;
        if (qi < nA) {
            int bj = bestg[q] * JGRP + (int)(__float_as_uint(bestv[q]) & 15u);
            float4 b = sBo[bj];
            float dx = ax[q] - b.x, dy = ay[q] - b.y, dz = az[q] - b.z;
            float d2 = fmaf(dx, dx, fmaf(dy, dy, dz * dz));
            unsigned long long key =
                (((unsigned long long)__float_as_uint(d2)) << 32) |
                (unsigned long long)__float_as_uint(b.w);
            g_partial_keys[dir][blockIdx.y][qi] = key;   // no atomics
        }
    }
}

// Stage 1: one thread per query (fwd then bwd concatenated); scan slab partials.
__global__ void __launch_bounds__(256) loss_stage1(
        const float* __restrict__ rsig, const float* __restrict__ ssig,
        int n, int m) {
    __shared__ float wsum[8];
    int idx = blockIdx.x * 256 + threadIdx.x;
    float acc = 0.0f;
    if (idx < n + m) {
        int dir = (idx < n) ? 0 : 1;
        int i = (idx < n) ? idx : idx - n;
        int nB = dir ? n : m;
        int njb = (nB + JTILE - 1) / JTILE;
        unsigned long long k = ~0ULL;
        for (int jb = 0; jb < njb; jb++) {
            unsigned long long v = g_partial_keys[dir][jb][i];
            k = (v < k) ? v : k;
        }
        float self = dir ? __ldg(&ssig[i]) : __ldg(&rsig[i]);
        float d   = sqrtf(__uint_as_float((unsigned)(k >> 32)));
        float sig = 0.5f * (self + __uint_as_float((unsigned)k));
        float inv = dir ? (1.0f / (float)m) : (1.0f / (float)n);
        acc = (__logf(sig) + __fdividef(d, sig)) * inv;
    }
#pragma unroll
    for (int o = 16; o > 0; o >>= 1)
        acc += __shfl_xor_sync(0xFFFFFFFF, acc, o);
    if ((threadIdx.x & 31) == 0) wsum[threadIdx.x >> 5] = acc;
    __syncthreads();
    if (threadIdx.x < 8) {
        float v = wsum[threadIdx.x];
#pragma unroll
        for (int o = 4; o > 0; o >>= 1)
            v += __shfl_xor_sync(0xFF, v, o);
        if (threadIdx.x == 0) g_partial_sums[blockIdx.x] = v;
    }
}

__global__ void loss_stage2(float* __restrict__ out, int nblocks) {
    int tid = threadIdx.x;   // 64 threads
    __shared__ float s2[2];
    float v = (tid < nblocks) ? g_partial_sums[tid] : 0.0f;
#pragma unroll
    for (int o = 16; o > 0; o >>= 1)
        v += __shfl_xor_sync(0xFFFFFFFF, v, o);
    if ((tid & 31) == 0) s2[tid >> 5] = v;
    __syncthreads();
    if (tid == 0) out[0] = s2[0] + s2[1];
}

extern "C" void kernel_launch(void* const* d_in, const int* in_sizes, int n_in,
                              void* d_out, int out_size) {
    const float* ref  = (const float*)d_in[0];
    const float* src  = (const float*)d_in[1];
    const float* T    = (const float*)d_in[2];
    const float* rsig = (const float*)d_in[3];
    const float* ssig = (const float*)d_in[4];
    int n = in_sizes[3];
    int m = in_sizes[4];

    int nm = n > m ? n : m;
    dim3 g((nm + QTILE - 1) / QTILE, (nm + JTILE - 1) / JTILE, 2);
    nn_pass<<<g, NTHR>>>(ref, src, T, rsig, ssig, n, m);

    int rblocks = (n + m + 255) / 256;
    loss_stage1<<<rblocks, 256>>>(rsig, ssig, n, m);
    loss_stage2<<<1, 64>>>((float*)d_out, rblocks);
}